// round 17
// baseline (speedup 1.0000x reference)
#include <cuda_runtime.h>

// AllReduce_77335181131889 — TP=4 sum + bias + residual + RMSNorm, fp32.
// R16: R14 with the stage-2 reduction bug fixed. The symmetric finish MUST
// start its xor-shuffle at off=16 so lanes 16-31 fold onto the partial-holding
// lanes 0-7 (off=8 kept the upper half-warp isolated -> s=0 -> scale~1000).
// Geometry: 256 thr x 4 CTAs/SM, hoisted bias/weight loads, single barrier.

#define T_DIM 8192
#define H_DIM 4096
#define H4    (H_DIM / 4)      // 1024 float4 per row
#define NTHREADS 256
#define VPT 4                  // float4 vectors per thread (256*4 = 1024)
#define NWARPS (NTHREADS / 32) // 8

__global__ __launch_bounds__(NTHREADS, 4)
void fused_ar_rmsnorm_kernel(const float4* __restrict__ x,      // [4*T*H4]
                             const float4* __restrict__ res,    // [T*H4]
                             const float4* __restrict__ bias,   // [H4]
                             const float4* __restrict__ w,      // [H4]
                             float4* __restrict__ norm_out,     // [T*H4]
                             float4* __restrict__ inter_out)    // [T*H4]
{
    const int row = blockIdx.x;
    const long rowOff = (long)row * H4;
    const long rs = (long)T_DIM * H4;   // rank stride in float4

    float4 inter[VPT];
    float4 wt[VPT];
    float ss = 0.0f;

    // Streaming load phase: 4 ranks + residual + bias + weight per vector.
    #pragma unroll
    for (int i = 0; i < VPT; i++) {
        const int col = threadIdx.x + i * NTHREADS;       // 0..1023
        const long p = rowOff + col;
        float4 a  = x[p];
        float4 b  = x[rs + p];
        float4 c  = x[2 * rs + p];
        float4 d  = x[3 * rs + p];
        float4 r  = res[p];
        float4 bi = bias[col];
        wt[i]     = w[col];          // hoisted: latency hidden under streams

        float4 v;
        v.x = ((a.x + b.x) + (c.x + d.x)) + (bi.x + r.x);
        v.y = ((a.y + b.y) + (c.y + d.y)) + (bi.y + r.y);
        v.z = ((a.z + b.z) + (c.z + d.z)) + (bi.z + r.z);
        v.w = ((a.w + b.w) + (c.w + d.w)) + (bi.w + r.w);

        ss = fmaf(v.x, v.x, ss);
        ss = fmaf(v.y, v.y, ss);
        ss = fmaf(v.z, v.z, ss);
        ss = fmaf(v.w, v.w, ss);

        inter[i] = v;
        inter_out[p] = v;   // stream intermediate out immediately
    }

    // Stage 1: warp-level reduction of sum of squares.
    #pragma unroll
    for (int off = 16; off > 0; off >>= 1)
        ss += __shfl_xor_sync(0xFFFFFFFFu, ss, off);

    __shared__ float warp_ss[NWARPS];
    const int wid = threadIdx.x >> 5;
    const int lid = threadIdx.x & 31;
    if (lid == 0) warp_ss[wid] = ss;
    __syncthreads();

    // Stage 2 (single barrier): every warp reduces the 8 partials itself.
    // Full 5-step xor reduce (off=16 first!) so ALL 32 lanes converge to the
    // block sum — offsets {8,4,2,1} alone never cross the half-warp boundary.
    float s = (lid < NWARPS) ? warp_ss[lid] : 0.0f;
    #pragma unroll
    for (int off = 16; off > 0; off >>= 1)
        s += __shfl_xor_sync(0xFFFFFFFFu, s, off);
    const float scale = rsqrtf(s * (1.0f / (float)H_DIM) + 1e-6f);

    // Tail: pure register math + stores (weights already resident).
    #pragma unroll
    for (int i = 0; i < VPT; i++) {
        const int col = threadIdx.x + i * NTHREADS;
        const long p = rowOff + col;
        float4 v = inter[i];
        float4 o;
        o.x = v.x * scale * wt[i].x;
        o.y = v.y * scale * wt[i].y;
        o.z = v.z * scale * wt[i].z;
        o.w = v.w * scale * wt[i].w;
        norm_out[p] = o;
    }
}

extern "C" void kernel_launch(void* const* d_in, const int* in_sizes, int n_in,
                              void* d_out, int out_size)
{
    const float4* x    = (const float4*)d_in[0];   // x_ranks [4,T,H]
    const float4* res  = (const float4*)d_in[1];   // residual [T,H]
    const float4* bias = (const float4*)d_in[2];   // bias [H]
    const float4* w    = (const float4*)d_in[3];   // norm_weight [H]

    float* out = (float*)d_out;
    float4* norm_out  = (float4*)out;                              // first T*H
    float4* inter_out = (float4*)(out + (long)T_DIM * H_DIM);      // second T*H

    fused_ar_rmsnorm_kernel<<<T_DIM, NTHREADS>>>(x, res, bias, w, norm_out, inter_out);
}